// round 2
// baseline (speedup 1.0000x reference)
#include <cuda_runtime.h>

#define B_  2
#define S_  128
#define D_  256
#define H_  8
#define E_  32
#define BH_ (B_*H_)   // 16

__device__ float g_xs[BH_ * S_ * E_];   // softmax'd projected activations, [bh][s][e]
__device__ float g_o [BH_ * S_ * E_];   // attn @ x result, [bh][s][e]

// ---- packed f32x2 helpers (sm_100+) ----
__device__ __forceinline__ unsigned long long pk2(float lo, float hi) {
    unsigned long long r;
    asm("mov.b64 %0, {%1,%2};" : "=l"(r) : "f"(lo), "f"(hi));
    return r;
}
__device__ __forceinline__ void unpk2(unsigned long long p, float& lo, float& hi) {
    asm("mov.b64 {%0,%1}, %2;" : "=f"(lo), "=f"(hi) : "l"(p));
}
__device__ __forceinline__ unsigned long long mul2(unsigned long long a, unsigned long long b) {
    unsigned long long r;
    asm("mul.rn.f32x2 %0, %1, %2;" : "=l"(r) : "l"(a), "l"(b));
    return r;
}
__device__ __forceinline__ unsigned long long fma2(unsigned long long a, unsigned long long b,
                                                   unsigned long long c) {
    unsigned long long r;
    asm("fma.rn.f32x2 %0, %1, %2, %3;" : "=l"(r) : "l"(a), "l"(b), "l"(c));
    return r;
}

// ---------------------------------------------------------------------------
// K1: thread-per-output GEMM (4 token rows / block) + fused per-head softmax.
// grid = 64, block = 256. Thread t = output column e; warp = head.
// ---------------------------------------------------------------------------
__global__ void k_proj_softmax(const float* __restrict__ inp,
                               const float* __restrict__ w_in,
                               const float* __restrict__ b_in) {
    __shared__ float xs[4][D_];
    const int blk = blockIdx.x;          // rows blk*4 .. blk*4+3  (row = b*S + s)
    const int t   = threadIdx.x;

    #pragma unroll
    for (int idx = t; idx < 4 * D_; idx += 256)
        xs[idx >> 8][idx & 255] = inp[blk * 4 * D_ + idx];
    __syncthreads();

    const int h = t >> 5, l = t & 31;
    const float4* wr = (const float4*)(w_in + t * D_);
    float a0 = 0.f, a1 = 0.f, a2 = 0.f, a3 = 0.f;
    #pragma unroll 8
    for (int k = 0; k < D_ / 4; ++k) {
        const float4 w  = wr[k];
        const float4 x0 = *(const float4*)&xs[0][4 * k];
        const float4 x1 = *(const float4*)&xs[1][4 * k];
        const float4 x2 = *(const float4*)&xs[2][4 * k];
        const float4 x3 = *(const float4*)&xs[3][4 * k];
        a0 = fmaf(w.x, x0.x, fmaf(w.y, x0.y, fmaf(w.z, x0.z, fmaf(w.w, x0.w, a0))));
        a1 = fmaf(w.x, x1.x, fmaf(w.y, x1.y, fmaf(w.z, x1.z, fmaf(w.w, x1.w, a1))));
        a2 = fmaf(w.x, x2.x, fmaf(w.y, x2.y, fmaf(w.z, x2.z, fmaf(w.w, x2.w, a2))));
        a3 = fmaf(w.x, x3.x, fmaf(w.y, x3.y, fmaf(w.z, x3.z, fmaf(w.w, x3.w, a3))));
    }
    const float bb = b_in[t];
    float acc[4] = { a0 + bb, a1 + bb, a2 + bb, a3 + bb };

    #pragma unroll
    for (int r = 0; r < 4; ++r) {
        float val = acc[r];
        float mx = val;
        #pragma unroll
        for (int o = 16; o > 0; o >>= 1)
            mx = fmaxf(mx, __shfl_xor_sync(0xffffffffu, mx, o));
        const float p = __expf(val - mx);
        float sm = p;
        #pragma unroll
        for (int o = 16; o > 0; o >>= 1)
            sm += __shfl_xor_sync(0xffffffffu, sm, o);
        const int row = blk * 4 + r, b = row >> 7, s = row & (S_ - 1);
        g_xs[(((b << 3) + h) * S_ + s) * E_ + l] = p / sm;
    }
}

// ---------------------------------------------------------------------------
// K2: spline scores + softmax over j + attn @ x.
// grid = (S, BH), 128 threads; thread t owns column j = t.
// Algebra: per e, sum_f [u*v + 0.5*u*v*m - m^3/6]  with  m=min(u,v)
//   =>  (softmax-invariant consts dropped)  s = sum_e 0.5*u_e*P_e - Q/6,
//       P_e = sum_f v_f*m,  Q = sum_ef m^3.   Packed f32x2 math.
// ---------------------------------------------------------------------------
__global__ void k_spline_attn() {
    __shared__ float xsh[S_ * 33];
    __shared__ float attn_sh[S_];
    __shared__ float red_mx[4];
    __shared__ float red_sm[4];
    __shared__ float pacc[4][E_];

    const int i  = blockIdx.x;
    const int bh = blockIdx.y;
    const int t  = threadIdx.x;

    const float* base = g_xs + bh * (S_ * E_);
    #pragma unroll
    for (int idx = t; idx < S_ * E_; idx += 128)
        xsh[(idx >> 5) * 33 + (idx & 31)] = base[idx];
    __syncthreads();

    float v[E_];
    unsigned long long vp[E_ / 2];
    #pragma unroll
    for (int f = 0; f < E_; ++f) v[f] = xsh[t * 33 + f];
    #pragma unroll
    for (int f = 0; f < E_ / 2; ++f) vp[f] = pk2(v[2 * f], v[2 * f + 1]);

    const float* u = xsh + i * 33;
    unsigned long long q0 = 0ull, q1 = 0ull;   // packed (0.f,0.f)
    float s = 0.f;

    for (int e = 0; e < E_; ++e) {
        const float a = u[e];                  // LDS broadcast
        unsigned long long p0 = 0ull, p1 = 0ull;
        #pragma unroll
        for (int fp = 0; fp < E_ / 2; fp += 2) {
            {
                const float m0 = fminf(a, v[2 * fp]);
                const float m1 = fminf(a, v[2 * fp + 1]);
                const unsigned long long m01 = pk2(m0, m1);
                p0 = fma2(m01, vp[fp], p0);
                const unsigned long long mm = mul2(m01, m01);
                q0 = fma2(mm, m01, q0);
            }
            {
                const float m0 = fminf(a, v[2 * fp + 2]);
                const float m1 = fminf(a, v[2 * fp + 3]);
                const unsigned long long m01 = pk2(m0, m1);
                p1 = fma2(m01, vp[fp + 1], p1);
                const unsigned long long mm = mul2(m01, m01);
                q1 = fma2(mm, m01, q1);
            }
        }
        float pa, pb, pc, pd;
        unpk2(p0, pa, pb);
        unpk2(p1, pc, pd);
        s = fmaf(0.5f * a, (pa + pb) + (pc + pd), s);
    }
    float qa, qb, qc, qd;
    unpk2(q0, qa, qb);
    unpk2(q1, qc, qd);
    const float logit = (s - ((qa + qb) + (qc + qd)) * (1.0f / 6.0f)) * (1.0f / (float)E_);

    // block softmax over 128 logits
    const int w = t >> 5, l = t & 31;
    float mx = logit;
    #pragma unroll
    for (int o = 16; o > 0; o >>= 1)
        mx = fmaxf(mx, __shfl_xor_sync(0xffffffffu, mx, o));
    if (l == 0) red_mx[w] = mx;
    __syncthreads();
    mx = fmaxf(fmaxf(red_mx[0], red_mx[1]), fmaxf(red_mx[2], red_mx[3]));

    const float p = __expf(logit - mx);
    float sm = p;
    #pragma unroll
    for (int o = 16; o > 0; o >>= 1)
        sm += __shfl_xor_sync(0xffffffffu, sm, o);
    if (l == 0) red_sm[w] = sm;
    __syncthreads();
    sm = (red_sm[0] + red_sm[1]) + (red_sm[2] + red_sm[3]);

    attn_sh[t] = p / sm;
    __syncthreads();

    // out[i, e] = sum_j attn[j] * x[j, e]
    {
        const int e = t & 31, part = t >> 5;
        float acc = 0.f;
        #pragma unroll
        for (int j0 = 0; j0 < 32; ++j0) {
            const int j = part * 32 + j0;
            acc = fmaf(attn_sh[j], xsh[j * 33 + e], acc);
        }
        pacc[part][e] = acc;
    }
    __syncthreads();
    if (t < E_) {
        const float r = (pacc[0][t] + pacc[1][t]) + (pacc[2][t] + pacc[3][t]);
        g_o[(bh * S_ + i) * E_ + t] = r;
    }
}

// ---------------------------------------------------------------------------
// K3: out = o @ w_out^T + b_out. Same GEMM skeleton as K1, gathered input.
// grid = 64, block = 256.
// ---------------------------------------------------------------------------
__global__ void k_out_proj(const float* __restrict__ w_out,
                           const float* __restrict__ b_out,
                           float* __restrict__ out) {
    __shared__ float xs[4][D_];
    const int blk = blockIdx.x;
    const int t   = threadIdx.x;

    #pragma unroll
    for (int idx = t; idx < 4 * D_; idx += 256) {
        const int r = idx >> 8, d = idx & 255;
        const int h = d >> 5, e = d & 31;
        const int row = blk * 4 + r, b = row >> 7, s = row & (S_ - 1);
        xs[r][d] = g_o[(((b << 3) + h) * S_ + s) * E_ + e];
    }
    __syncthreads();

    const float4* wr = (const float4*)(w_out + t * D_);
    float a0 = 0.f, a1 = 0.f, a2 = 0.f, a3 = 0.f;
    #pragma unroll 8
    for (int k = 0; k < D_ / 4; ++k) {
        const float4 w  = wr[k];
        const float4 x0 = *(const float4*)&xs[0][4 * k];
        const float4 x1 = *(const float4*)&xs[1][4 * k];
        const float4 x2 = *(const float4*)&xs[2][4 * k];
        const float4 x3 = *(const float4*)&xs[3][4 * k];
        a0 = fmaf(w.x, x0.x, fmaf(w.y, x0.y, fmaf(w.z, x0.z, fmaf(w.w, x0.w, a0))));
        a1 = fmaf(w.x, x1.x, fmaf(w.y, x1.y, fmaf(w.z, x1.z, fmaf(w.w, x1.w, a1))));
        a2 = fmaf(w.x, x2.x, fmaf(w.y, x2.y, fmaf(w.z, x2.z, fmaf(w.w, x2.w, a2))));
        a3 = fmaf(w.x, x3.x, fmaf(w.y, x3.y, fmaf(w.z, x3.z, fmaf(w.w, x3.w, a3))));
    }
    const float bb = b_out[t];
    out[(blk * 4 + 0) * D_ + t] = a0 + bb;
    out[(blk * 4 + 1) * D_ + t] = a1 + bb;
    out[(blk * 4 + 2) * D_ + t] = a2 + bb;
    out[(blk * 4 + 3) * D_ + t] = a3 + bb;
}

extern "C" void kernel_launch(void* const* d_in, const int* in_sizes, int n_in,
                              void* d_out, int out_size) {
    const float* inp   = (const float*)d_in[0];
    const float* w_in  = (const float*)d_in[1];
    const float* b_in  = (const float*)d_in[2];
    const float* w_out = (const float*)d_in[3];
    const float* b_out = (const float*)d_in[4];
    float* out = (float*)d_out;
    (void)in_sizes; (void)n_in; (void)out_size;

    k_proj_softmax<<<B_ * S_ / 4, 256>>>(inp, w_in, b_in);
    k_spline_attn<<<dim3(S_, BH_), 128>>>();
    k_out_proj<<<B_ * S_ / 4, 256>>>(w_out, b_out, out);
}

// round 3
// speedup vs baseline: 1.2137x; 1.2137x over previous
#include <cuda_runtime.h>

#define B_  2
#define S_  128
#define D_  256
#define H_  8
#define E_  32
#define BH_ 16
#define ITILE 8

__device__ float  g_xs[BH_ * S_ * E_];    // softmaxed x, original e-order
__device__ float  g_sv[BH_ * S_ * E_];    // per-row sorted values (asc)
__device__ float4 g_pfx[BH_ * S_ * 33];   // per-row rank tables
__device__ float  g_o [BH_ * S_ * E_];    // attn @ x

static const int SMEM_GEMM   = (16 * 256 + 32 * 257) * 4;                       // 49280
static const int SMEM_SPLINE = (128 * 33 + ITILE * 32) * 16 + (128 * 33 * 2) * 4
                             + (256 + 8 + 8 + 256) * 4;                          // 107584

// ---- warp helpers ----
__device__ __forceinline__ float wmax(float v) {
    #pragma unroll
    for (int o = 16; o > 0; o >>= 1) v = fmaxf(v, __shfl_xor_sync(0xffffffffu, v, o));
    return v;
}
__device__ __forceinline__ float wsum(float v) {
    #pragma unroll
    for (int o = 16; o > 0; o >>= 1) v += __shfl_xor_sync(0xffffffffu, v, o);
    return v;
}
__device__ __forceinline__ float bitonic32(float v, int l) {
    #pragma unroll
    for (int k = 2; k <= 32; k <<= 1) {
        #pragma unroll
        for (int j = k >> 1; j > 0; j >>= 1) {
            const float o = __shfl_xor_sync(0xffffffffu, v, j);
            const bool up = ((l & k) == 0);
            const bool lower = ((l & j) == 0);
            v = (lower == up) ? fminf(v, o) : fmaxf(v, o);
        }
    }
    return v;
}
__device__ __forceinline__ float iscan(float x, int l) {
    #pragma unroll
    for (int o = 1; o < 32; o <<= 1) {
        const float n = __shfl_up_sync(0xffffffffu, x, o);
        if (l >= o) x += n;
    }
    return x;
}

// ---------------------------------------------------------------------------
// K1: tiled GEMM (16 rows x 32 cols/block) + per-head softmax + sort + scans.
// grid (16 row-tiles, 8 heads), 128 threads. Warp = 32 cols x 4 rows.
// ---------------------------------------------------------------------------
__global__ void k_proj(const float* __restrict__ inp,
                       const float* __restrict__ w_in,
                       const float* __restrict__ b_in) {
    extern __shared__ float smem[];
    float* xs = smem;              // [16][256]
    float* ws = smem + 16 * 256;   // [32][257]

    const int t  = threadIdx.x;
    const int r0 = blockIdx.x * 16;
    const int hd = blockIdx.y;
    const int c0 = hd * 32;

    #pragma unroll
    for (int f = t; f < 16 * 64; f += 128) {
        const int r = f >> 6, kq = f & 63;
        *(float4*)(xs + r * 256 + kq * 4) = *(const float4*)(inp + (r0 + r) * 256 + kq * 4);
    }
    {
        const int kk = t & 31, cg = t >> 5;
        #pragma unroll
        for (int it = 0; it < 8; ++it) {
            const int cc = cg * 8 + it;
            #pragma unroll
            for (int kh = 0; kh < 2; ++kh) {
                const int k4 = kh * 32 + kk;
                const float4 v = *(const float4*)(w_in + (c0 + cc) * 256 + k4 * 4);
                float* dst = ws + cc * 257 + k4 * 4;
                dst[0] = v.x; dst[1] = v.y; dst[2] = v.z; dst[3] = v.w;
            }
        }
    }
    __syncthreads();

    const int cc = t & 31, rg = t >> 5;
    const float* wrow = ws + cc * 257;
    float acc[4] = {0.f, 0.f, 0.f, 0.f};
    #pragma unroll 4
    for (int kq = 0; kq < 64; ++kq) {
        const float w0 = wrow[4 * kq + 0], w1 = wrow[4 * kq + 1];
        const float w2 = wrow[4 * kq + 2], w3 = wrow[4 * kq + 3];
        #pragma unroll
        for (int rr = 0; rr < 4; ++rr) {
            const float4 x4 = *(const float4*)(xs + (rg * 4 + rr) * 256 + 4 * kq);
            acc[rr] = fmaf(w0, x4.x, fmaf(w1, x4.y, fmaf(w2, x4.z, fmaf(w3, x4.w, acc[rr]))));
        }
    }
    const float bb = b_in[c0 + cc];
    const int l = cc;

    #pragma unroll
    for (int rr = 0; rr < 4; ++rr) {
        const float val = acc[rr] + bb;
        const float mx = wmax(val);
        float p = __expf(val - mx);
        const float sm = wsum(p);
        p = p / sm;

        const int row = r0 + rg * 4 + rr;
        const int b = row >> 7, s = row & 127;
        const int bh = b * 8 + hd;
        const int rowo = (bh * 128 + s);
        g_xs[rowo * 32 + l] = p;

        const float v  = bitonic32(p, l);
        g_sv[rowo * 32 + l] = v;
        const float v2 = v * v, v3 = v2 * v;
        const float s1 = iscan(v, l);
        const float s2 = iscan(v2, l);
        const float s3 = iscan(v3, l);
        const float T1 = __shfl_sync(0xffffffffu, s1, 31);

        float4 q;
        q.x = T1 - (s1 - v);            // suffix sum of v from rank l
        q.y = 0.5f * (s2 - v2);         // 0.5 * prefix of v^2 below rank l
        q.z = -(s3 - v3) * (1.f / 6.f); // -prefix of v^3 / 6
        q.w = (float)l - 32.f;          // -(32 - r)
        g_pfx[rowo * 33 + l] = q;
        if (l == 31) {
            float4 q2;
            q2.x = T1 - s1;             // = 0
            q2.y = 0.5f * s2;
            q2.z = -s3 * (1.f / 6.f);
            q2.w = 0.f;
            g_pfx[rowo * 33 + 32] = q2;
        }
    }
}

// ---------------------------------------------------------------------------
// K2: spline attention via rank tables. grid (16 i-tiles, 16 bh), 256 threads.
// Thread = (j = t&127, half = t>>7); each half handles 4 i's.
// ---------------------------------------------------------------------------
__global__ void k_spline() {
    extern __shared__ char smem_raw[];
    float4* pfxq = (float4*)smem_raw;                 // [128*33]
    float4* uq   = pfxq + 128 * 33;                   // [ITILE*32]
    float*  sv   = (float*)(uq + ITILE * 32);         // [128*33]
    float*  xsh  = sv + 128 * 33;                     // [128*33]
    float*  attn = xsh + 128 * 33;                    // [2][128]
    float*  redm = attn + 256;                        // [2][4]
    float*  reds = redm + 8;                          // [2][4]
    float*  pacc = reds + 8;                          // [2][4][32]

    const int t  = threadIdx.x;
    const int bh = blockIdx.y;
    const int i0 = blockIdx.x * ITILE;

    for (int idx = t; idx < 128 * 33; idx += 256)
        pfxq[idx] = g_pfx[bh * (128 * 33) + idx];
    for (int g = t; g < 128 * 32; g += 256) {
        const int j = g >> 5, k = g & 31;
        sv [j * 33 + k] = g_sv[bh * 4096 + g];
        xsh[j * 33 + k] = g_xs[bh * 4096 + g];
    }
    __syncthreads();
    {
        const int il = t >> 5, e = t & 31;   // 8*32 = 256
        const float u = xsh[(i0 + il) * 33 + e];
        uq[il * 32 + e] = make_float4(u, 0.5f * u * u, u * u * u * (1.f / 6.f), 0.f);
    }
    __syncthreads();

    const int j = t & 127, half = t >> 7;
    const int w4 = (t >> 5) & 3, l = t & 31;
    const float*  svj = sv + j * 33;
    const float4* pfj = pfxq + j * 33;

    for (int ii = 0; ii < 4; ++ii) {
        const int il = half * 4 + ii;
        const float4* uqr = uq + il * 32;
        float a0 = 0.f, a1 = 0.f;
        #pragma unroll 8
        for (int e = 0; e < 32; e += 2) {
            {
                const float4 uu = uqr[e];
                const float u = uu.x;
                int r = (svj[15] < u) ? 16 : 0;
                r += (svj[r + 7] < u) ? 8 : 0;
                r += (svj[r + 3] < u) ? 4 : 0;
                r += (svj[r + 1] < u) ? 2 : 0;
                r += (svj[r]     < u) ? 1 : 0;
                r += (svj[r]     < u) ? 1 : 0;
                const float4 q = pfj[r];
                a0 = fmaf(uu.y, q.x, a0);
                a0 = fmaf(uu.x, q.y, a0);
                a0 = fmaf(uu.z, q.w, a0);
                a0 += q.z;
            }
            {
                const float4 uu = uqr[e + 1];
                const float u = uu.x;
                int r = (svj[15] < u) ? 16 : 0;
                r += (svj[r + 7] < u) ? 8 : 0;
                r += (svj[r + 3] < u) ? 4 : 0;
                r += (svj[r + 1] < u) ? 2 : 0;
                r += (svj[r]     < u) ? 1 : 0;
                r += (svj[r]     < u) ? 1 : 0;
                const float4 q = pfj[r];
                a1 = fmaf(uu.y, q.x, a1);
                a1 = fmaf(uu.x, q.y, a1);
                a1 = fmaf(uu.z, q.w, a1);
                a1 += q.z;
            }
        }
        const float logit = (a0 + a1) * (1.f / 32.f);

        float mx = wmax(logit);
        if (l == 0) redm[half * 4 + w4] = mx;
        __syncthreads();
        const float* rm = redm + half * 4;
        mx = fmaxf(fmaxf(rm[0], rm[1]), fmaxf(rm[2], rm[3]));
        const float p = __expf(logit - mx);
        float sm = wsum(p);
        if (l == 0) reds[half * 4 + w4] = sm;
        __syncthreads();
        const float* rs = reds + half * 4;
        sm = (rs[0] + rs[1]) + (rs[2] + rs[3]);
        attn[half * 128 + j] = p / sm;
        __syncthreads();

        // out[i,e] = sum_j attn[j] * x[j,e]
        {
            const int e = j & 31, strip = j >> 5;
            float oa = 0.f;
            #pragma unroll
            for (int jj = 0; jj < 32; ++jj) {
                const int js = strip * 32 + jj;
                oa = fmaf(attn[half * 128 + js], xsh[js * 33 + e], oa);
            }
            pacc[(half * 4 + strip) * 32 + e] = oa;
        }
        __syncthreads();
        if (j < 32) {
            const float* pb = pacc + half * 4 * 32;
            const float r4 = (pb[j] + pb[32 + j]) + (pb[64 + j] + pb[96 + j]);
            g_o[(bh * 128 + i0 + il) * 32 + j] = r4;
        }
        __syncthreads();
    }
}

// ---------------------------------------------------------------------------
// K3: out = o @ w_out^T + b_out. Same tiled GEMM, gathered x.
// ---------------------------------------------------------------------------
__global__ void k_out(const float* __restrict__ w_out,
                      const float* __restrict__ b_out,
                      float* __restrict__ out) {
    extern __shared__ float smem[];
    float* xs = smem;
    float* ws = smem + 16 * 256;

    const int t  = threadIdx.x;
    const int r0 = blockIdx.x * 16;
    const int c0 = blockIdx.y * 32;

    #pragma unroll
    for (int f = t; f < 16 * 64; f += 128) {
        const int r = f >> 6, kq = f & 63;
        const int row = r0 + r, b = row >> 7, s = row & 127;
        const int d = kq * 4, h = d >> 5, e = d & 31;
        *(float4*)(xs + r * 256 + kq * 4) =
            *(const float4*)(g_o + ((b * 8 + h) * 128 + s) * 32 + e);
    }
    {
        const int kk = t & 31, cg = t >> 5;
        #pragma unroll
        for (int it = 0; it < 8; ++it) {
            const int cc = cg * 8 + it;
            #pragma unroll
            for (int kh = 0; kh < 2; ++kh) {
                const int k4 = kh * 32 + kk;
                const float4 v = *(const float4*)(w_out + (c0 + cc) * 256 + k4 * 4);
                float* dst = ws + cc * 257 + k4 * 4;
                dst[0] = v.x; dst[1] = v.y; dst[2] = v.z; dst[3] = v.w;
            }
        }
    }
    __syncthreads();

    const int cc = t & 31, rg = t >> 5;
    const float* wrow = ws + cc * 257;
    float acc[4] = {0.f, 0.f, 0.f, 0.f};
    #pragma unroll 4
    for (int kq = 0; kq < 64; ++kq) {
        const float w0 = wrow[4 * kq + 0], w1 = wrow[4 * kq + 1];
        const float w2 = wrow[4 * kq + 2], w3 = wrow[4 * kq + 3];
        #pragma unroll
        for (int rr = 0; rr < 4; ++rr) {
            const float4 x4 = *(const float4*)(xs + (rg * 4 + rr) * 256 + 4 * kq);
            acc[rr] = fmaf(w0, x4.x, fmaf(w1, x4.y, fmaf(w2, x4.z, fmaf(w3, x4.w, acc[rr]))));
        }
    }
    const float bb = b_out[c0 + cc];
    #pragma unroll
    for (int rr = 0; rr < 4; ++rr)
        out[(r0 + rg * 4 + rr) * 256 + c0 + cc] = acc[rr] + bb;
}

extern "C" void kernel_launch(void* const* d_in, const int* in_sizes, int n_in,
                              void* d_out, int out_size) {
    const float* inp   = (const float*)d_in[0];
    const float* w_in  = (const float*)d_in[1];
    const float* b_in  = (const float*)d_in[2];
    const float* w_out = (const float*)d_in[3];
    const float* b_out = (const float*)d_in[4];
    float* out = (float*)d_out;
    (void)in_sizes; (void)n_in; (void)out_size;

    cudaFuncSetAttribute(k_proj,   cudaFuncAttributeMaxDynamicSharedMemorySize, SMEM_GEMM);
    cudaFuncSetAttribute(k_spline, cudaFuncAttributeMaxDynamicSharedMemorySize, SMEM_SPLINE);
    cudaFuncSetAttribute(k_out,    cudaFuncAttributeMaxDynamicSharedMemorySize, SMEM_GEMM);

    k_proj<<<dim3(16, 8), 128, SMEM_GEMM>>>(inp, w_in, b_in);
    k_spline<<<dim3(S_ / ITILE, BH_), 256, SMEM_SPLINE>>>();
    k_out<<<dim3(16, 8), 128, SMEM_GEMM>>>(w_out, b_out, out);
}

// round 4
// speedup vs baseline: 1.3894x; 1.1448x over previous
#include <cuda_runtime.h>

#define BH_ 16

// gmem scratch (zero-init device globals; slot-32 pads stay 0 = deterministic)
__device__ float g_xs[BH_ * 128 * 33];   // softmaxed x (33-stride, slot32 unused)
__device__ float g_sv[BH_ * 128 * 33];   // sorted values
__device__ float g_qA[BH_ * 128 * 33];   // suffix sum of v      (coeff of 0.5u^2)
__device__ float g_qB[BH_ * 128 * 33];   // 0.5 * prefix v^2     (coeff of u)
__device__ float g_qC[BH_ * 128 * 33];   // -prefix v^3 / 6      (constant)
__device__ float g_lg[BH_ * 128 * 128];  // raw logits
__device__ float g_o [BH_ * 128 * 32];   // attn @ x

static const int SMEM_GEMM = (4096 + 32 * 257 + 512) * 4;   // 51328
static const int SMEM_SPL  = 5 * 4224 * 4;                  // 84480
static const int SMEM_AV   = (4224 + 1024) * 4;             // 20992

__device__ __forceinline__ float wmax(float v) {
    #pragma unroll
    for (int o = 16; o > 0; o >>= 1) v = fmaxf(v, __shfl_xor_sync(0xffffffffu, v, o));
    return v;
}
__device__ __forceinline__ float wsum(float v) {
    #pragma unroll
    for (int o = 16; o > 0; o >>= 1) v += __shfl_xor_sync(0xffffffffu, v, o);
    return v;
}
__device__ __forceinline__ float bitonic32(float v, int l) {
    #pragma unroll
    for (int k = 2; k <= 32; k <<= 1) {
        #pragma unroll
        for (int j = k >> 1; j > 0; j >>= 1) {
            const float o = __shfl_xor_sync(0xffffffffu, v, j);
            const bool up = ((l & k) == 0);
            const bool lower = ((l & j) == 0);
            v = (lower == up) ? fminf(v, o) : fmaxf(v, o);
        }
    }
    return v;
}
__device__ __forceinline__ float iscan(float x, int l) {
    #pragma unroll
    for (int o = 1; o < 32; o <<= 1) {
        const float n = __shfl_up_sync(0xffffffffu, x, o);
        if (l >= o) x += n;
    }
    return x;
}

// ---------------------------------------------------------------------------
// K1: in-projection GEMM (16 rows x 32 cols, K split over warp-halves)
//     + per-head softmax + sort + prefix tables.  grid(16,8), 256 thr.
// ---------------------------------------------------------------------------
__global__ void k_proj(const float* __restrict__ inp,
                       const float* __restrict__ w_in,
                       const float* __restrict__ b_in) {
    extern __shared__ float sm[];
    float* xs = sm;             // [16][256]
    float* ws = sm + 4096;      // [32][257]
    float* ps = ws + 32 * 257;  // [16][32]

    const int t = threadIdx.x, lane = t & 31, wid = t >> 5;
    const int r0 = blockIdx.x * 16, hd = blockIdx.y, c0 = hd * 32;

    #pragma unroll
    for (int f = t; f < 1024; f += 256) {
        const int r = f >> 6, kq = f & 63;
        *(float4*)(xs + r * 256 + kq * 4) = *(const float4*)(inp + (r0 + r) * 256 + kq * 4);
    }
    #pragma unroll
    for (int rr = 0; rr < 4; ++rr) {
        const int cc = wid * 4 + rr;
        #pragma unroll
        for (int hh = 0; hh < 2; ++hh) {
            const int k4 = hh * 32 + lane;
            const float4 v = *(const float4*)(w_in + (c0 + cc) * 256 + k4 * 4);
            float* d = ws + cc * 257 + k4 * 4;
            d[0] = v.x; d[1] = v.y; d[2] = v.z; d[3] = v.w;
        }
    }
    __syncthreads();

    const int kh = wid >> 2, rg = wid & 3;
    const float* wrow = ws + lane * 257 + kh * 128;
    const float* xb   = xs + rg * 4 * 256 + kh * 128;
    float acc[4] = {0.f, 0.f, 0.f, 0.f};
    #pragma unroll 8
    for (int kq = 0; kq < 32; ++kq) {
        const float w0 = wrow[4 * kq + 0], w1 = wrow[4 * kq + 1];
        const float w2 = wrow[4 * kq + 2], w3 = wrow[4 * kq + 3];
        #pragma unroll
        for (int rr = 0; rr < 4; ++rr) {
            const float4 x4 = *(const float4*)(xb + rr * 256 + 4 * kq);
            acc[rr] = fmaf(w0, x4.x, fmaf(w1, x4.y, fmaf(w2, x4.z, fmaf(w3, x4.w, acc[rr]))));
        }
    }
    if (kh == 1) {
        #pragma unroll
        for (int rr = 0; rr < 4; ++rr) ps[(rg * 4 + rr) * 32 + lane] = acc[rr];
    }
    __syncthreads();
    if (kh == 0) {
        const float bb = b_in[c0 + lane];
        #pragma unroll
        for (int rr = 0; rr < 4; ++rr) {
            const float val = acc[rr] + ps[(rg * 4 + rr) * 32 + lane] + bb;
            const float mx = wmax(val);
            float p = __expf(val - mx);
            const float smv = wsum(p);
            p = p / smv;

            const int row = r0 + rg * 4 + rr;
            const int b = row >> 7, s = row & 127;
            const int rowo = (b * 8 + hd) * 128 + s;
            g_xs[rowo * 33 + lane] = p;

            const float v  = bitonic32(p, lane);
            g_sv[rowo * 33 + lane] = v;
            const float v2 = v * v, v3 = v2 * v;
            const float s1 = iscan(v, lane);
            const float s2 = iscan(v2, lane);
            const float s3 = iscan(v3, lane);
            const float T1 = __shfl_sync(0xffffffffu, s1, 31);

            g_qA[rowo * 33 + lane] = T1 - (s1 - v);
            g_qB[rowo * 33 + lane] = 0.5f * (s2 - v2);
            g_qC[rowo * 33 + lane] = -(s3 - v3) * (1.f / 6.f);
            if (lane == 31) {
                g_qA[rowo * 33 + 32] = 0.f;
                g_qB[rowo * 33 + 32] = 0.5f * s2;
                g_qC[rowo * 33 + 32] = -s3 * (1.f / 6.f);
            }
        }
    }
}

// ---------------------------------------------------------------------------
// K2a: spline logits via rank tables. Symmetric: warp handles i and 127-i,
//      j >= i only, mirrored writes. grid(8 itile, 16 bh), 256 thr (8 warps).
//      lane = e: search in sv_j is conflict-free (shared row, distinct ranks).
// ---------------------------------------------------------------------------
__global__ void k_spline() {
    extern __shared__ float sm[];
    float* qA  = sm;
    float* qB  = qA + 4224;
    float* qC  = qB + 4224;
    float* sv  = qC + 4224;
    float* xsh = sv + 4224;

    const int t = threadIdx.x, lane = t & 31, wid = t >> 5;
    const int bh = blockIdx.y;
    const int base = bh * 4224;
    for (int idx = t; idx < 4224; idx += 256) {
        qA[idx]  = g_qA[base + idx];
        qB[idx]  = g_qB[base + idx];
        qC[idx]  = g_qC[base + idx];
        sv[idx]  = g_sv[base + idx];
        xsh[idx] = g_xs[base + idx];
    }
    __syncthreads();

    float* LG = g_lg + bh * 16384;

    #pragma unroll
    for (int half = 0; half < 2; ++half) {
        const int i = half ? (127 - (blockIdx.x * 8 + wid)) : (blockIdx.x * 8 + wid);
        const float u  = xsh[i * 33 + lane];
        const float u2 = 0.5f * u * u;
        const float u3 = u * u * u * (1.f / 6.f);

        #pragma unroll 4
        for (int j = i; j < 128; ++j) {
            const float* svj = sv + j * 33;
            int r = (svj[15] < u) ? 16 : 0;
            r += (svj[r + 7] < u) ? 8 : 0;
            r += (svj[r + 3] < u) ? 4 : 0;
            r += (svj[r + 1] < u) ? 2 : 0;
            r += (svj[r]     < u) ? 1 : 0;
            r += (svj[r]     < u) ? 1 : 0;
            const int o = j * 33 + r;
            float val = fmaf(u2, qA[o], fmaf(u, qB[o], fmaf(u3, (float)r, qC[o])));
            val = wsum(val);
            if (lane == 0) {
                LG[i * 128 + j] = val;
                LG[j * 128 + i] = val;
            }
        }
    }
}

// ---------------------------------------------------------------------------
// K2b: per-row softmax over j + out = attn @ x. grid(16,16), 256 thr.
// ---------------------------------------------------------------------------
__global__ void k_attn_av() {
    extern __shared__ float sm[];
    float* xsh  = sm;          // 4224
    float* attn = sm + 4224;   // [8][128]

    const int t = threadIdx.x, lane = t & 31, wid = t >> 5;
    const int bh = blockIdx.y, i = blockIdx.x * 8 + wid;
    const int base = bh * 4224;
    for (int idx = t; idx < 4224; idx += 256) xsh[idx] = g_xs[base + idx];
    __syncthreads();

    const float4 lg4 = *(const float4*)(g_lg + bh * 16384 + i * 128 + lane * 4);
    const float l0 = lg4.x * (1.f / 32.f), l1 = lg4.y * (1.f / 32.f);
    const float l2 = lg4.z * (1.f / 32.f), l3 = lg4.w * (1.f / 32.f);
    float mx = fmaxf(fmaxf(l0, l1), fmaxf(l2, l3));
    mx = wmax(mx);
    const float e0 = __expf(l0 - mx), e1 = __expf(l1 - mx);
    const float e2 = __expf(l2 - mx), e3 = __expf(l3 - mx);
    float s = (e0 + e1) + (e2 + e3);
    s = wsum(s);
    const float inv = 1.f / s;
    float* at = attn + wid * 128;
    *(float4*)(at + lane * 4) = make_float4(e0 * inv, e1 * inv, e2 * inv, e3 * inv);
    __syncwarp();

    float acc = 0.f;
    #pragma unroll 8
    for (int j = 0; j < 128; ++j)
        acc = fmaf(at[j], xsh[j * 33 + lane], acc);
    g_o[(bh * 128 + i) * 32 + lane] = acc;
}

// ---------------------------------------------------------------------------
// K3: out = o @ w_out^T + b_out. Same K-split GEMM as K1. grid(16,8), 256 thr.
// ---------------------------------------------------------------------------
__global__ void k_out(const float* __restrict__ w_out,
                      const float* __restrict__ b_out,
                      float* __restrict__ out) {
    extern __shared__ float sm[];
    float* xs = sm;
    float* ws = sm + 4096;
    float* ps = ws + 32 * 257;

    const int t = threadIdx.x, lane = t & 31, wid = t >> 5;
    const int r0 = blockIdx.x * 16, c0 = blockIdx.y * 32;

    #pragma unroll
    for (int f = t; f < 1024; f += 256) {
        const int r = f >> 6, kq = f & 63;
        const int row = r0 + r, b = row >> 7, s = row & 127;
        const int d = kq * 4, h = d >> 5, e = d & 31;
        *(float4*)(xs + r * 256 + kq * 4) =
            *(const float4*)(g_o + ((b * 8 + h) * 128 + s) * 32 + e);
    }
    #pragma unroll
    for (int rr = 0; rr < 4; ++rr) {
        const int cc = wid * 4 + rr;
        #pragma unroll
        for (int hh = 0; hh < 2; ++hh) {
            const int k4 = hh * 32 + lane;
            const float4 v = *(const float4*)(w_out + (c0 + cc) * 256 + k4 * 4);
            float* d = ws + cc * 257 + k4 * 4;
            d[0] = v.x; d[1] = v.y; d[2] = v.z; d[3] = v.w;
        }
    }
    __syncthreads();

    const int kh = wid >> 2, rg = wid & 3;
    const float* wrow = ws + lane * 257 + kh * 128;
    const float* xb   = xs + rg * 4 * 256 + kh * 128;
    float acc[4] = {0.f, 0.f, 0.f, 0.f};
    #pragma unroll 8
    for (int kq = 0; kq < 32; ++kq) {
        const float w0 = wrow[4 * kq + 0], w1 = wrow[4 * kq + 1];
        const float w2 = wrow[4 * kq + 2], w3 = wrow[4 * kq + 3];
        #pragma unroll
        for (int rr = 0; rr < 4; ++rr) {
            const float4 x4 = *(const float4*)(xb + rr * 256 + 4 * kq);
            acc[rr] = fmaf(w0, x4.x, fmaf(w1, x4.y, fmaf(w2, x4.z, fmaf(w3, x4.w, acc[rr]))));
        }
    }
    if (kh == 1) {
        #pragma unroll
        for (int rr = 0; rr < 4; ++rr) ps[(rg * 4 + rr) * 32 + lane] = acc[rr];
    }
    __syncthreads();
    if (kh == 0) {
        const float bb = b_out[c0 + lane];
        #pragma unroll
        for (int rr = 0; rr < 4; ++rr)
            out[(r0 + rg * 4 + rr) * 256 + c0 + lane] =
                acc[rr] + ps[(rg * 4 + rr) * 32 + lane] + bb;
    }
}

extern "C" void kernel_launch(void* const* d_in, const int* in_sizes, int n_in,
                              void* d_out, int out_size) {
    const float* inp   = (const float*)d_in[0];
    const float* w_in  = (const float*)d_in[1];
    const float* b_in  = (const float*)d_in[2];
    const float* w_out = (const float*)d_in[3];
    const float* b_out = (const float*)d_in[4];
    float* out = (float*)d_out;
    (void)in_sizes; (void)n_in; (void)out_size;

    cudaFuncSetAttribute(k_proj,    cudaFuncAttributeMaxDynamicSharedMemorySize, SMEM_GEMM);
    cudaFuncSetAttribute(k_spline,  cudaFuncAttributeMaxDynamicSharedMemorySize, SMEM_SPL);
    cudaFuncSetAttribute(k_attn_av, cudaFuncAttributeMaxDynamicSharedMemorySize, SMEM_AV);
    cudaFuncSetAttribute(k_out,     cudaFuncAttributeMaxDynamicSharedMemorySize, SMEM_GEMM);

    k_proj   <<<dim3(16, 8),  256, SMEM_GEMM>>>(inp, w_in, b_in);
    k_spline <<<dim3(8, 16),  256, SMEM_SPL>>>();
    k_attn_av<<<dim3(16, 16), 256, SMEM_AV>>>();
    k_out    <<<dim3(16, 8),  256, SMEM_GEMM>>>(w_out, b_out, out);
}